// round 1
// baseline (speedup 1.0000x reference)
#include <cuda_runtime.h>
#include <math.h>

#define SEQL   2048
#define BATCH  2
#define DMODEL 1024
#define NHEADS 16
#define DHEAD  64
#define MR     (BATCH * SEQL)   // 4096 total rows
#define NSEG   16
#define SEGROWS (SEQL / NSEG)   // 128

// ---------------- scratch (device globals; no runtime allocation) ----------------
__device__ float g_Q[(size_t)MR * DMODEL];          // LN(X Wq^T)
__device__ float g_K[(size_t)MR * DMODEL];          // LN(X Wk^T)
__device__ float g_V[(size_t)MR * DMODEL];          // X Wv^T
__device__ float g_F[(size_t)BATCH * SEQL * SEQL];  // C then F (in-place scan)
__device__ float g_P[(size_t)BATCH * NSEG * SEQL];  // segment partial sums
__device__ float g_O[(size_t)MR * DMODEL];          // attention output (b,n,h*dh)

// ---------------- generic SGEMM: Y[M,N] = A[M,K] * B[N,K]^T ----------------
// 128x128 tile, BK=16, 256 threads, 8x8 per thread.
__global__ __launch_bounds__(256) void gemm_nt(const float* __restrict__ A,
                                               const float* __restrict__ B,
                                               float* __restrict__ Y,
                                               int M, int N, int K) {
    __shared__ float As[128][17];
    __shared__ float Bs[128][17];
    const int tid = threadIdx.x;
    const int tx = tid & 15, ty = tid >> 4;
    const int m0 = blockIdx.y * 128, n0 = blockIdx.x * 128;

    float acc[8][8] = {};
    for (int k0 = 0; k0 < K; k0 += 16) {
#pragma unroll
        for (int t = 0; t < 8; t++) {
            int idx = tid + t * 256;          // 0..2047
            int r = idx >> 4, c = idx & 15;
            As[r][c] = A[(size_t)(m0 + r) * K + k0 + c];
            Bs[r][c] = B[(size_t)(n0 + r) * K + k0 + c];
        }
        __syncthreads();
#pragma unroll
        for (int kk = 0; kk < 16; kk++) {
            float a[8], b[8];
#pragma unroll
            for (int i = 0; i < 8; i++) a[i] = As[ty * 8 + i][kk];
#pragma unroll
            for (int j = 0; j < 8; j++) b[j] = Bs[tx * 8 + j][kk];
#pragma unroll
            for (int i = 0; i < 8; i++)
#pragma unroll
                for (int j = 0; j < 8; j++) acc[i][j] += a[i] * b[j];
        }
        __syncthreads();
    }
#pragma unroll
    for (int i = 0; i < 8; i++)
#pragma unroll
        for (int j = 0; j < 8; j++)
            Y[(size_t)(m0 + ty * 8 + i) * N + n0 + tx * 8 + j] = acc[i][j];
}

// ---------------- row LayerNorm (in place), one block per row of 1024 ----------------
__global__ __launch_bounds__(256) void ln_rows(float* __restrict__ Y,
                                               const float* __restrict__ g,
                                               const float* __restrict__ b) {
    const int row = blockIdx.x;
    float* y = Y + (size_t)row * DMODEL;
    __shared__ float red[256];

    float s = 0.f;
    for (int i = threadIdx.x; i < DMODEL; i += 256) s += y[i];
    red[threadIdx.x] = s;
    __syncthreads();
    for (int o = 128; o > 0; o >>= 1) {
        if (threadIdx.x < o) red[threadIdx.x] += red[threadIdx.x + o];
        __syncthreads();
    }
    const float mu = red[0] * (1.0f / DMODEL);
    __syncthreads();

    float v = 0.f;
    for (int i = threadIdx.x; i < DMODEL; i += 256) {
        float d = y[i] - mu;
        v += d * d;
    }
    red[threadIdx.x] = v;
    __syncthreads();
    for (int o = 128; o > 0; o >>= 1) {
        if (threadIdx.x < o) red[threadIdx.x] += red[threadIdx.x + o];
        __syncthreads();
    }
    const float rstd = rsqrtf(red[0] * (1.0f / DMODEL) + 1e-5f);
    __syncthreads();

    for (int i = threadIdx.x; i < DMODEL; i += 256)
        y[i] = (y[i] - mu) * rstd * g[i] + b[i];
}

// ---------------- head-0 scores: C[b,r,m] = relu(q0[r]·k0[m]/8) for 1<=m<r else 0 ----------------
__global__ __launch_bounds__(256) void head0_scores() {
    const int b = blockIdx.z;
    const int r0 = blockIdx.y * 64, m0 = blockIdx.x * 64;
    __shared__ float Qs[64][65];
    __shared__ float Ks[64][65];
    const int tid = threadIdx.x;
    const int tx = tid & 15, ty = tid >> 4;

#pragma unroll
    for (int t = 0; t < 16; t++) {
        int idx = tid + t * 256;          // 0..4095
        int rr = idx >> 6, cc = idx & 63;
        Qs[rr][cc] = g_Q[(size_t)(b * SEQL + r0 + rr) * DMODEL + cc];
        Ks[rr][cc] = g_K[(size_t)(b * SEQL + m0 + rr) * DMODEL + cc];
    }
    __syncthreads();

    float acc[4][4] = {};
#pragma unroll 8
    for (int k = 0; k < 64; k++) {
        float a[4], bv[4];
#pragma unroll
        for (int i = 0; i < 4; i++) a[i] = Qs[ty * 4 + i][k];
#pragma unroll
        for (int j = 0; j < 4; j++) bv[j] = Ks[tx * 4 + j][k];
#pragma unroll
        for (int i = 0; i < 4; i++)
#pragma unroll
            for (int j = 0; j < 4; j++) acc[i][j] += a[i] * bv[j];
    }
#pragma unroll
    for (int i = 0; i < 4; i++)
#pragma unroll
        for (int j = 0; j < 4; j++) {
            int r = r0 + ty * 4 + i;
            int m = m0 + tx * 4 + j;
            float v = acc[i][j] * 0.125f;
            v = (m >= 1 && m < r) ? fmaxf(v, 0.f) : 0.f;
            g_F[(size_t)(b * SEQL + r) * SEQL + m] = v;
        }
}

// ---------------- 3-pass exclusive column scan over rows: F[n,m] = sum_{r<n} C[r,m] ----------------
__global__ __launch_bounds__(256) void seg_sum() {
    const int m = blockIdx.x * 256 + threadIdx.x;
    const int seg = blockIdx.y, b = blockIdx.z;
    const float* base = g_F + (size_t)(b * SEQL + seg * SEGROWS) * SEQL + m;
    float s = 0.f;
#pragma unroll 4
    for (int r = 0; r < SEGROWS; r++) s += base[(size_t)r * SEQL];
    g_P[(size_t)(b * NSEG + seg) * SEQL + m] = s;
}

__global__ __launch_bounds__(256) void seg_scan() {
    const int m = blockIdx.x * 256 + threadIdx.x;
    const int b = blockIdx.y;
    float acc = 0.f;
#pragma unroll
    for (int s = 0; s < NSEG; s++) {
        size_t idx = (size_t)(b * NSEG + s) * SEQL + m;
        float v = g_P[idx];
        g_P[idx] = acc;
        acc += v;
    }
}

__global__ __launch_bounds__(256) void final_scan() {
    const int m = blockIdx.x * 256 + threadIdx.x;
    const int seg = blockIdx.y, b = blockIdx.z;
    float acc = g_P[(size_t)(b * NSEG + seg) * SEQL + m];
    float* base = g_F + (size_t)(b * SEQL + seg * SEGROWS) * SEQL + m;
#pragma unroll 4
    for (int r = 0; r < SEGROWS; r++) {
        float c = base[(size_t)r * SEQL];
        base[(size_t)r * SEQL] = acc;
        acc += c;
    }
}

// ---------------- flash attention with F-mask ----------------
// 64 query rows per block, 64-key tiles, 256 threads, 4x4 per thread.
// Online softmax entirely in registers + warp shuffles (row split over 16 lanes).
__device__ __forceinline__ int swz(int r, int c) { return r * 64 + (c ^ (r & 31)); }

__global__ __launch_bounds__(256) void attn_kernel() {
    __shared__ float Qs[64 * 64];   // swizzled
    __shared__ float Ks[64 * 64];   // swizzled K, then plain P
    __shared__ float Vs[64 * 64];   // plain [m][d]
    const int b = blockIdx.z, h = blockIdx.y;
    const int q0 = blockIdx.x * 64;
    const int tid = threadIdx.x;
    const int tx = tid & 15, ty = tid >> 4;

#pragma unroll
    for (int t = 0; t < 16; t++) {
        int idx = tid + t * 256;
        int rr = idx >> 6, cc = idx & 63;
        Qs[swz(rr, cc)] = g_Q[(size_t)(b * SEQL + q0 + rr) * DMODEL + h * DHEAD + cc];
    }
    float row_m[4], row_l[4];
    float o[4][4] = {};
#pragma unroll
    for (int i = 0; i < 4; i++) { row_m[i] = -1e30f; row_l[i] = 0.f; }
    __syncthreads();

    const int nkt = q0 / 64 + 1;   // causal: only key tiles up to the query tile
    for (int kt = 0; kt < nkt; kt++) {
        const int m0 = kt * 64;
#pragma unroll
        for (int t = 0; t < 16; t++) {
            int idx = tid + t * 256;
            int rr = idx >> 6, cc = idx & 63;
            Ks[swz(rr, cc)] = g_K[(size_t)(b * SEQL + m0 + rr) * DMODEL + h * DHEAD + cc];
            Vs[rr * 64 + cc] = g_V[(size_t)(b * SEQL + m0 + rr) * DMODEL + h * DHEAD + cc];
        }
        __syncthreads();

        float s[4][4] = {};
#pragma unroll 8
        for (int k = 0; k < 64; k++) {
            float a[4], bv[4];
#pragma unroll
            for (int i = 0; i < 4; i++) a[i] = Qs[swz(ty * 4 + i, k)];
#pragma unroll
            for (int j = 0; j < 4; j++) bv[j] = Ks[swz(tx * 4 + j, k)];
#pragma unroll
            for (int i = 0; i < 4; i++)
#pragma unroll
                for (int j = 0; j < 4; j++) s[i][j] += a[i] * bv[j];
        }
        __syncthreads();   // done reading K; P will overwrite Ks

#pragma unroll
        for (int i = 0; i < 4; i++) {
            const int r = q0 + ty * 4 + i;
            const float* Frow = g_F + (size_t)(b * SEQL + r) * SEQL + m0 + tx * 4;
            float mx_t = -1e30f;
#pragma unroll
            for (int j = 0; j < 4; j++) {
                int m = m0 + tx * 4 + j;
                float v = s[i][j] * 0.125f - Frow[j];
                if (m > r) v = -1e30f;
                s[i][j] = v;
                mx_t = fmaxf(mx_t, v);
            }
#pragma unroll
            for (int d = 1; d < 16; d <<= 1)
                mx_t = fmaxf(mx_t, __shfl_xor_sync(0xffffffffu, mx_t, d));
            const float mx = fmaxf(row_m[i], mx_t);
            const float sc = __expf(row_m[i] - mx);
            float psum = 0.f;
#pragma unroll
            for (int j = 0; j < 4; j++) {
                float e = __expf(s[i][j] - mx);
                s[i][j] = e;
                psum += e;
            }
#pragma unroll
            for (int d = 1; d < 16; d <<= 1)
                psum += __shfl_xor_sync(0xffffffffu, psum, d);
            row_l[i] = row_l[i] * sc + psum;
            row_m[i] = mx;
#pragma unroll
            for (int j = 0; j < 4; j++) o[i][j] *= sc;
#pragma unroll
            for (int j = 0; j < 4; j++)
                Ks[(ty * 4 + i) * 64 + tx * 4 + j] = s[i][j];
        }
        __syncthreads();

#pragma unroll 8
        for (int k = 0; k < 64; k++) {
            float p[4], v[4];
#pragma unroll
            for (int i = 0; i < 4; i++) p[i] = Ks[(ty * 4 + i) * 64 + k];
#pragma unroll
            for (int j = 0; j < 4; j++) v[j] = Vs[k * 64 + tx * 4 + j];
#pragma unroll
            for (int i = 0; i < 4; i++)
#pragma unroll
                for (int j = 0; j < 4; j++) o[i][j] += p[i] * v[j];
        }
        __syncthreads();
    }

#pragma unroll
    for (int i = 0; i < 4; i++) {
        const int r = q0 + ty * 4 + i;
        const float inv = 1.0f / row_l[i];
#pragma unroll
        for (int j = 0; j < 4; j++)
            g_O[(size_t)(b * SEQL + r) * DMODEL + h * DHEAD + tx * 4 + j] = o[i][j] * inv;
    }
}

// ---------------- launch ----------------
extern "C" void kernel_launch(void* const* d_in, const int* in_sizes, int n_in,
                              void* d_out, int out_size) {
    const float* X  = (const float*)d_in[0];
    const float* Wq = (const float*)d_in[1];
    const float* Wk = (const float*)d_in[2];
    const float* Wv = (const float*)d_in[3];
    const float* Wo = (const float*)d_in[4];
    const float* gq = (const float*)d_in[5];
    const float* bq = (const float*)d_in[6];
    const float* gk = (const float*)d_in[7];
    const float* bk = (const float*)d_in[8];
    // d_in[9] cache_k, d_in[10] cache_v, d_in[11] start_pos (= 0) — unused
    float* out = (float*)d_out;

    float *pQ, *pK, *pV, *pO;
    cudaGetSymbolAddress((void**)&pQ, g_Q);
    cudaGetSymbolAddress((void**)&pK, g_K);
    cudaGetSymbolAddress((void**)&pV, g_V);
    cudaGetSymbolAddress((void**)&pO, g_O);

    const dim3 gemm_grid(DMODEL / 128, MR / 128);   // (8, 32)

    gemm_nt<<<gemm_grid, 256>>>(X, Wq, pQ, MR, DMODEL, DMODEL);
    gemm_nt<<<gemm_grid, 256>>>(X, Wk, pK, MR, DMODEL, DMODEL);
    gemm_nt<<<gemm_grid, 256>>>(X, Wv, pV, MR, DMODEL, DMODEL);

    ln_rows<<<MR, 256>>>(pQ, gq, bq);
    ln_rows<<<MR, 256>>>(pK, gk, bk);

    head0_scores<<<dim3(SEQL / 64, SEQL / 64, BATCH), 256>>>();
    seg_sum<<<dim3(SEQL / 256, NSEG, BATCH), 256>>>();
    seg_scan<<<dim3(SEQL / 256, BATCH), 256>>>();
    final_scan<<<dim3(SEQL / 256, NSEG, BATCH), 256>>>();

    attn_kernel<<<dim3(SEQL / 64, NHEADS, BATCH), 256>>>();

    gemm_nt<<<gemm_grid, 256>>>(pO, Wo, out, MR, DMODEL, DMODEL);
}

// round 2
// speedup vs baseline: 2.3230x; 2.3230x over previous
#include <cuda_runtime.h>
#include <math.h>

#define SEQL   2048
#define BATCH  2
#define DMODEL 1024
#define NHEADS 16
#define DHEAD  64
#define MR     (BATCH * SEQL)   // 4096 rows
#define NSEG   16
#define SEGROWS (SEQL / NSEG)   // 128

// ---------------- scratch ----------------
__device__ float g_Q[(size_t)MR * DMODEL];
__device__ float g_K[(size_t)MR * DMODEL];
__device__ float g_V[(size_t)MR * DMODEL];
__device__ float g_F[(size_t)BATCH * SEQL * SEQL];
__device__ float g_P[(size_t)BATCH * NSEG * SEQL];
__device__ float g_O[(size_t)MR * DMODEL];

// ---------------- tf32 mma helpers ----------------
__device__ __forceinline__ unsigned f2t(float x) {
    unsigned r;
    asm("cvt.rna.tf32.f32 %0, %1;" : "=r"(r) : "f"(x));
    return r;
}

#define MMA(C, A0, A1, A2, A3, B0, B1)                                         \
    asm volatile(                                                              \
        "mma.sync.aligned.m16n8k8.row.col.f32.tf32.tf32.f32 "                  \
        "{%0,%1,%2,%3},{%4,%5,%6,%7},{%8,%9},{%0,%1,%2,%3};"                   \
        : "+f"((C)[0]), "+f"((C)[1]), "+f"((C)[2]), "+f"((C)[3])               \
        : "r"(A0), "r"(A1), "r"(A2), "r"(A3), "r"(B0), "r"(B1))

// ---------------- GEMM: Y[M,N] = A[M,K]·B[N,K]^T, tf32 mma ----------------
// 128x128 tile, BK=32, 256 threads (8 warps, 2x4), warp tile 64x32.
// SPLIT=3 -> 3xTF32 (fp32-class accuracy); SPLIT=1 -> plain tf32.
template <int SPLIT>
__global__ __launch_bounds__(256) void gemm_tf32(const float* __restrict__ A,
                                                 const float* __restrict__ B,
                                                 float* __restrict__ Y,
                                                 int M, int N, int K) {
    __shared__ float As[128][36];
    __shared__ float Bs[128][36];
    const int tid = threadIdx.x, lane = tid & 31, warp = tid >> 5;
    const int g = lane >> 2, tg = lane & 3;
    const int wm = warp >> 2, wn = warp & 3;
    const int m0 = blockIdx.y * 128, n0 = blockIdx.x * 128;
    const int lrow = tid >> 3, lcol = (tid & 7) * 4;

    float c[4][4][4] = {};

    for (int k0 = 0; k0 < K; k0 += 32) {
#pragma unroll
        for (int it = 0; it < 4; it++) {
            int r = lrow + it * 32;
            *(float4*)&As[r][lcol] = *(const float4*)&A[(size_t)(m0 + r) * K + k0 + lcol];
            *(float4*)&Bs[r][lcol] = *(const float4*)&B[(size_t)(n0 + r) * K + k0 + lcol];
        }
        __syncthreads();
#pragma unroll
        for (int kc = 0; kc < 4; kc++) {
            unsigned bh[4][2], bl[4][2];
#pragma unroll
            for (int ni = 0; ni < 4; ni++) {
                int nb = wn * 32 + ni * 8;
                float b0 = Bs[nb + g][kc * 8 + tg];
                float b1 = Bs[nb + g][kc * 8 + tg + 4];
                bh[ni][0] = f2t(b0);
                bh[ni][1] = f2t(b1);
                if (SPLIT == 3) {
                    bl[ni][0] = f2t(b0 - __uint_as_float(bh[ni][0]));
                    bl[ni][1] = f2t(b1 - __uint_as_float(bh[ni][1]));
                }
            }
#pragma unroll
            for (int mi = 0; mi < 4; mi++) {
                int rm = wm * 64 + mi * 16;
                float a0 = As[rm + g][kc * 8 + tg];
                float a1 = As[rm + g + 8][kc * 8 + tg];
                float a2 = As[rm + g][kc * 8 + tg + 4];
                float a3 = As[rm + g + 8][kc * 8 + tg + 4];
                unsigned ah0 = f2t(a0), ah1 = f2t(a1), ah2 = f2t(a2), ah3 = f2t(a3);
                unsigned al0 = 0, al1 = 0, al2 = 0, al3 = 0;
                if (SPLIT == 3) {
                    al0 = f2t(a0 - __uint_as_float(ah0));
                    al1 = f2t(a1 - __uint_as_float(ah1));
                    al2 = f2t(a2 - __uint_as_float(ah2));
                    al3 = f2t(a3 - __uint_as_float(ah3));
                }
#pragma unroll
                for (int ni = 0; ni < 4; ni++) {
                    MMA(c[mi][ni], ah0, ah1, ah2, ah3, bh[ni][0], bh[ni][1]);
                    if (SPLIT == 3) {
                        MMA(c[mi][ni], ah0, ah1, ah2, ah3, bl[ni][0], bl[ni][1]);
                        MMA(c[mi][ni], al0, al1, al2, al3, bh[ni][0], bh[ni][1]);
                    }
                }
            }
        }
        __syncthreads();
    }

#pragma unroll
    for (int mi = 0; mi < 4; mi++)
#pragma unroll
        for (int ni = 0; ni < 4; ni++) {
            int r = m0 + wm * 64 + mi * 16 + g;
            int col = n0 + wn * 32 + ni * 8 + 2 * tg;
            *(float2*)&Y[(size_t)r * N + col] = make_float2(c[mi][ni][0], c[mi][ni][1]);
            *(float2*)&Y[(size_t)(r + 8) * N + col] = make_float2(c[mi][ni][2], c[mi][ni][3]);
        }
}

// ---------------- row LayerNorm (unchanged) ----------------
__global__ __launch_bounds__(256) void ln_rows(float* __restrict__ Y,
                                               const float* __restrict__ g,
                                               const float* __restrict__ b) {
    const int row = blockIdx.x;
    float* y = Y + (size_t)row * DMODEL;
    __shared__ float red[256];

    float s = 0.f;
    for (int i = threadIdx.x; i < DMODEL; i += 256) s += y[i];
    red[threadIdx.x] = s;
    __syncthreads();
    for (int o = 128; o > 0; o >>= 1) {
        if (threadIdx.x < o) red[threadIdx.x] += red[threadIdx.x + o];
        __syncthreads();
    }
    const float mu = red[0] * (1.0f / DMODEL);
    __syncthreads();

    float v = 0.f;
    for (int i = threadIdx.x; i < DMODEL; i += 256) {
        float d = y[i] - mu;
        v += d * d;
    }
    red[threadIdx.x] = v;
    __syncthreads();
    for (int o = 128; o > 0; o >>= 1) {
        if (threadIdx.x < o) red[threadIdx.x] += red[threadIdx.x + o];
        __syncthreads();
    }
    const float rstd = rsqrtf(red[0] * (1.0f / DMODEL) + 1e-5f);
    __syncthreads();

    for (int i = threadIdx.x; i < DMODEL; i += 256)
        y[i] = (y[i] - mu) * rstd * g[i] + b[i];
}

// ---------------- head-0 scores via 3xTF32 mma ----------------
// C[b,r,m] = relu(q0[r]·k0[m]/8) for 1<=m<r else 0.  128x128 tile, K=64.
__global__ __launch_bounds__(256) void head0_tc() {
    __shared__ float As[128][36];
    __shared__ float Bs[128][36];
    const int tid = threadIdx.x, lane = tid & 31, warp = tid >> 5;
    const int g = lane >> 2, tg = lane & 3;
    const int wm = warp >> 2, wn = warp & 3;
    const int bb = blockIdx.z;
    const int r0 = blockIdx.y * 128, mm0 = blockIdx.x * 128;
    const float* Aq = g_Q + (size_t)(bb * SEQL + r0) * DMODEL;
    const float* Bk = g_K + (size_t)(bb * SEQL + mm0) * DMODEL;
    const int lrow = tid >> 3, lcol = (tid & 7) * 4;

    float c[4][4][4] = {};

    for (int k0 = 0; k0 < 64; k0 += 32) {
#pragma unroll
        for (int it = 0; it < 4; it++) {
            int r = lrow + it * 32;
            *(float4*)&As[r][lcol] = *(const float4*)&Aq[(size_t)r * DMODEL + k0 + lcol];
            *(float4*)&Bs[r][lcol] = *(const float4*)&Bk[(size_t)r * DMODEL + k0 + lcol];
        }
        __syncthreads();
#pragma unroll
        for (int kc = 0; kc < 4; kc++) {
            unsigned bh[4][2], bl[4][2];
#pragma unroll
            for (int ni = 0; ni < 4; ni++) {
                int nb = wn * 32 + ni * 8;
                float b0 = Bs[nb + g][kc * 8 + tg];
                float b1 = Bs[nb + g][kc * 8 + tg + 4];
                bh[ni][0] = f2t(b0);
                bh[ni][1] = f2t(b1);
                bl[ni][0] = f2t(b0 - __uint_as_float(bh[ni][0]));
                bl[ni][1] = f2t(b1 - __uint_as_float(bh[ni][1]));
            }
#pragma unroll
            for (int mi = 0; mi < 4; mi++) {
                int rm = wm * 64 + mi * 16;
                float a0 = As[rm + g][kc * 8 + tg];
                float a1 = As[rm + g + 8][kc * 8 + tg];
                float a2 = As[rm + g][kc * 8 + tg + 4];
                float a3 = As[rm + g + 8][kc * 8 + tg + 4];
                unsigned ah0 = f2t(a0), ah1 = f2t(a1), ah2 = f2t(a2), ah3 = f2t(a3);
                unsigned al0 = f2t(a0 - __uint_as_float(ah0));
                unsigned al1 = f2t(a1 - __uint_as_float(ah1));
                unsigned al2 = f2t(a2 - __uint_as_float(ah2));
                unsigned al3 = f2t(a3 - __uint_as_float(ah3));
#pragma unroll
                for (int ni = 0; ni < 4; ni++) {
                    MMA(c[mi][ni], ah0, ah1, ah2, ah3, bh[ni][0], bh[ni][1]);
                    MMA(c[mi][ni], ah0, ah1, ah2, ah3, bl[ni][0], bl[ni][1]);
                    MMA(c[mi][ni], al0, al1, al2, al3, bh[ni][0], bh[ni][1]);
                }
            }
        }
        __syncthreads();
    }

#pragma unroll
    for (int mi = 0; mi < 4; mi++)
#pragma unroll
        for (int ni = 0; ni < 4; ni++) {
            int r1 = r0 + wm * 64 + mi * 16 + g;
            int r2 = r1 + 8;
            int m = mm0 + wn * 32 + ni * 8 + 2 * tg;
            float v0 = c[mi][ni][0] * 0.125f;
            float v1 = c[mi][ni][1] * 0.125f;
            float v2 = c[mi][ni][2] * 0.125f;
            float v3 = c[mi][ni][3] * 0.125f;
            v0 = (m >= 1 && m < r1) ? fmaxf(v0, 0.f) : 0.f;
            v1 = (m + 1 < r1) ? fmaxf(v1, 0.f) : 0.f;
            v2 = (m >= 1 && m < r2) ? fmaxf(v2, 0.f) : 0.f;
            v3 = (m + 1 < r2) ? fmaxf(v3, 0.f) : 0.f;
            *(float2*)&g_F[(size_t)(bb * SEQL + r1) * SEQL + m] = make_float2(v0, v1);
            *(float2*)&g_F[(size_t)(bb * SEQL + r2) * SEQL + m] = make_float2(v2, v3);
        }
}

// ---------------- 3-pass exclusive column scan (unchanged) ----------------
__global__ __launch_bounds__(256) void seg_sum() {
    const int m = blockIdx.x * 256 + threadIdx.x;
    const int seg = blockIdx.y, b = blockIdx.z;
    const float* base = g_F + (size_t)(b * SEQL + seg * SEGROWS) * SEQL + m;
    float s = 0.f;
#pragma unroll 4
    for (int r = 0; r < SEGROWS; r++) s += base[(size_t)r * SEQL];
    g_P[(size_t)(b * NSEG + seg) * SEQL + m] = s;
}

__global__ __launch_bounds__(256) void seg_scan() {
    const int m = blockIdx.x * 256 + threadIdx.x;
    const int b = blockIdx.y;
    float acc = 0.f;
#pragma unroll
    for (int s = 0; s < NSEG; s++) {
        size_t idx = (size_t)(b * NSEG + s) * SEQL + m;
        float v = g_P[idx];
        g_P[idx] = acc;
        acc += v;
    }
}

__global__ __launch_bounds__(256) void final_scan() {
    const int m = blockIdx.x * 256 + threadIdx.x;
    const int seg = blockIdx.y, b = blockIdx.z;
    float acc = g_P[(size_t)(b * NSEG + seg) * SEQL + m];
    float* base = g_F + (size_t)(b * SEQL + seg * SEGROWS) * SEQL + m;
#pragma unroll 4
    for (int r = 0; r < SEGROWS; r++) {
        float c = base[(size_t)r * SEQL];
        base[(size_t)r * SEQL] = acc;
        acc += c;
    }
}

// ---------------- flash attention on tensor pipe ----------------
// 64 q-rows per block, 4 warps (16 rows each), 64-key tiles.
// QK: 1x tf32 (logit abs err ~2e-4, softmax-safe). PV: 3xTF32 (fp32-class).
__global__ __launch_bounds__(128) void attn_tc() {
    __shared__ float KP[64][68];  // K tile, then P tile
    __shared__ float Vs[64][72];
    const int b = blockIdx.z, h = blockIdx.y;
    const int qt = (int)gridDim.x - 1 - (int)blockIdx.x;  // longest blocks first
    const int q0 = qt * 64;
    const int tid = threadIdx.x, lane = tid & 31, w = tid >> 5;
    const int g = lane >> 2, tg = lane & 3;

    // stage Q through KP, pull A-fragments to registers
#pragma unroll
    for (int t = 0; t < 8; t++) {
        int fidx = tid + t * 128;          // 0..1023 float4s
        int row = fidx >> 4, col4 = (fidx & 15) * 4;
        *(float4*)&KP[row][col4] =
            *(const float4*)&g_Q[(size_t)(b * SEQL + q0 + row) * DMODEL + h * DHEAD + col4];
    }
    __syncthreads();
    unsigned qa[8][4];
#pragma unroll
    for (int kc = 0; kc < 8; kc++) {
        int rm = w * 16;
        qa[kc][0] = f2t(KP[rm + g][kc * 8 + tg]);
        qa[kc][1] = f2t(KP[rm + g + 8][kc * 8 + tg]);
        qa[kc][2] = f2t(KP[rm + g][kc * 8 + tg + 4]);
        qa[kc][3] = f2t(KP[rm + g + 8][kc * 8 + tg + 4]);
    }
    __syncthreads();

    float o[8][4] = {};
    float qm[2] = {-1e30f, -1e30f};
    float ql[2] = {0.f, 0.f};

    for (int kt = 0; kt <= qt; kt++) {
        const int m0 = kt * 64;
#pragma unroll
        for (int t = 0; t < 8; t++) {
            int fidx = tid + t * 128;
            int row = fidx >> 4, col4 = (fidx & 15) * 4;
            *(float4*)&KP[row][col4] =
                *(const float4*)&g_K[(size_t)(b * SEQL + m0 + row) * DMODEL + h * DHEAD + col4];
            *(float4*)&Vs[row][col4] =
                *(const float4*)&g_V[(size_t)(b * SEQL + m0 + row) * DMODEL + h * DHEAD + col4];
        }
        __syncthreads();

        // S = Q·K^T
        float sc[8][4] = {};
#pragma unroll
        for (int kc = 0; kc < 8; kc++) {
#pragma unroll
            for (int ni = 0; ni < 8; ni++) {
                unsigned b0 = f2t(KP[ni * 8 + g][kc * 8 + tg]);
                unsigned b1 = f2t(KP[ni * 8 + g][kc * 8 + tg + 4]);
                MMA(sc[ni], qa[kc][0], qa[kc][1], qa[kc][2], qa[kc][3], b0, b1);
            }
        }
        __syncthreads();  // done reading K

        // online softmax (rows r1=q0+w*16+g, r2=r1+8; quad = tg group)
        const bool diag = (kt == qt);
        const int lr1 = w * 16 + g, lr2 = lr1 + 8;
        const size_t frow1 = (size_t)(b * SEQL + q0 + lr1) * SEQL + m0;
        const size_t frow2 = (size_t)(b * SEQL + q0 + lr2) * SEQL + m0;
        float mx0 = -1e30f, mx1 = -1e30f;
#pragma unroll
        for (int ni = 0; ni < 8; ni++) {
            int cl = ni * 8 + 2 * tg;
            float2 f1 = *(const float2*)&g_F[frow1 + cl];
            float2 f2 = *(const float2*)&g_F[frow2 + cl];
            float v0 = sc[ni][0] * 0.125f - f1.x;
            float v1 = sc[ni][1] * 0.125f - f1.y;
            float v2 = sc[ni][2] * 0.125f - f2.x;
            float v3 = sc[ni][3] * 0.125f - f2.y;
            if (diag) {
                if (cl > lr1) v0 = -1e30f;
                if (cl + 1 > lr1) v1 = -1e30f;
                if (cl > lr2) v2 = -1e30f;
                if (cl + 1 > lr2) v3 = -1e30f;
            }
            sc[ni][0] = v0; sc[ni][1] = v1; sc[ni][2] = v2; sc[ni][3] = v3;
            mx0 = fmaxf(mx0, fmaxf(v0, v1));
            mx1 = fmaxf(mx1, fmaxf(v2, v3));
        }
        mx0 = fmaxf(mx0, __shfl_xor_sync(0xffffffffu, mx0, 1));
        mx0 = fmaxf(mx0, __shfl_xor_sync(0xffffffffu, mx0, 2));
        mx1 = fmaxf(mx1, __shfl_xor_sync(0xffffffffu, mx1, 1));
        mx1 = fmaxf(mx1, __shfl_xor_sync(0xffffffffu, mx1, 2));
        const float nm0 = fmaxf(qm[0], mx0), nm1 = fmaxf(qm[1], mx1);
        const float s0 = __expf(qm[0] - nm0), s1 = __expf(qm[1] - nm1);
        float ps0 = 0.f, ps1 = 0.f;
#pragma unroll
        for (int ni = 0; ni < 8; ni++) {
            float e0 = __expf(sc[ni][0] - nm0);
            float e1 = __expf(sc[ni][1] - nm0);
            float e2 = __expf(sc[ni][2] - nm1);
            float e3 = __expf(sc[ni][3] - nm1);
            sc[ni][0] = e0; sc[ni][1] = e1; sc[ni][2] = e2; sc[ni][3] = e3;
            ps0 += e0 + e1;
            ps1 += e2 + e3;
            o[ni][0] *= s0; o[ni][1] *= s0; o[ni][2] *= s1; o[ni][3] *= s1;
        }
        ps0 += __shfl_xor_sync(0xffffffffu, ps0, 1);
        ps0 += __shfl_xor_sync(0xffffffffu, ps0, 2);
        ps1 += __shfl_xor_sync(0xffffffffu, ps1, 1);
        ps1 += __shfl_xor_sync(0xffffffffu, ps1, 2);
        ql[0] = ql[0] * s0 + ps0;
        ql[1] = ql[1] * s1 + ps1;
        qm[0] = nm0; qm[1] = nm1;

        // write P into KP
#pragma unroll
        for (int ni = 0; ni < 8; ni++) {
            int cl = ni * 8 + 2 * tg;
            *(float2*)&KP[lr1][cl] = make_float2(sc[ni][0], sc[ni][1]);
            *(float2*)&KP[lr2][cl] = make_float2(sc[ni][2], sc[ni][3]);
        }
        __syncthreads();

        // O += P·V  (3xTF32)
#pragma unroll
        for (int kc = 0; kc < 8; kc++) {
            float p0 = KP[w * 16 + g][kc * 8 + tg];
            float p1 = KP[w * 16 + g + 8][kc * 8 + tg];
            float p2 = KP[w * 16 + g][kc * 8 + tg + 4];
            float p3 = KP[w * 16 + g + 8][kc * 8 + tg + 4];
            unsigned ph0 = f2t(p0), ph1 = f2t(p1), ph2 = f2t(p2), ph3 = f2t(p3);
            unsigned pl0 = f2t(p0 - __uint_as_float(ph0));
            unsigned pl1 = f2t(p1 - __uint_as_float(ph1));
            unsigned pl2 = f2t(p2 - __uint_as_float(ph2));
            unsigned pl3 = f2t(p3 - __uint_as_float(ph3));
#pragma unroll
            for (int ni = 0; ni < 8; ni++) {
                float v0 = Vs[kc * 8 + tg][ni * 8 + g];
                float v1 = Vs[kc * 8 + tg + 4][ni * 8 + g];
                unsigned vh0 = f2t(v0), vh1 = f2t(v1);
                unsigned vl0 = f2t(v0 - __uint_as_float(vh0));
                unsigned vl1 = f2t(v1 - __uint_as_float(vh1));
                MMA(o[ni], ph0, ph1, ph2, ph3, vh0, vh1);
                MMA(o[ni], ph0, ph1, ph2, ph3, vl0, vl1);
                MMA(o[ni], pl0, pl1, pl2, pl3, vh0, vh1);
            }
        }
        __syncthreads();
    }

    const float i0 = 1.0f / ql[0], i1 = 1.0f / ql[1];
    const int r1 = q0 + w * 16 + g, r2 = r1 + 8;
#pragma unroll
    for (int ni = 0; ni < 8; ni++) {
        int cl = h * DHEAD + ni * 8 + 2 * tg;
        *(float2*)&g_O[(size_t)(b * SEQL + r1) * DMODEL + cl] =
            make_float2(o[ni][0] * i0, o[ni][1] * i0);
        *(float2*)&g_O[(size_t)(b * SEQL + r2) * DMODEL + cl] =
            make_float2(o[ni][2] * i1, o[ni][3] * i1);
    }
}

// ---------------- launch ----------------
extern "C" void kernel_launch(void* const* d_in, const int* in_sizes, int n_in,
                              void* d_out, int out_size) {
    const float* X  = (const float*)d_in[0];
    const float* Wq = (const float*)d_in[1];
    const float* Wk = (const float*)d_in[2];
    const float* Wv = (const float*)d_in[3];
    const float* Wo = (const float*)d_in[4];
    const float* gq = (const float*)d_in[5];
    const float* bq = (const float*)d_in[6];
    const float* gk = (const float*)d_in[7];
    const float* bk = (const float*)d_in[8];
    float* out = (float*)d_out;

    float *pQ, *pK, *pV, *pO;
    cudaGetSymbolAddress((void**)&pQ, g_Q);
    cudaGetSymbolAddress((void**)&pK, g_K);
    cudaGetSymbolAddress((void**)&pV, g_V);
    cudaGetSymbolAddress((void**)&pO, g_O);

    const dim3 gemm_grid(DMODEL / 128, MR / 128);   // (8, 32)

    gemm_tf32<3><<<gemm_grid, 256>>>(X, Wq, pQ, MR, DMODEL, DMODEL);
    gemm_tf32<3><<<gemm_grid, 256>>>(X, Wk, pK, MR, DMODEL, DMODEL);
    gemm_tf32<3><<<gemm_grid, 256>>>(X, Wv, pV, MR, DMODEL, DMODEL);

    ln_rows<<<MR, 256>>>(pQ, gq, bq);
    ln_rows<<<MR, 256>>>(pK, gk, bk);

    head0_tc<<<dim3(SEQL / 128, SEQL / 128, BATCH), 256>>>();
    seg_sum<<<dim3(SEQL / 256, NSEG, BATCH), 256>>>();
    seg_scan<<<dim3(SEQL / 256, BATCH), 256>>>();
    final_scan<<<dim3(SEQL / 256, NSEG, BATCH), 256>>>();

    attn_tc<<<dim3(SEQL / 64, NHEADS, BATCH), 128>>>();

    gemm_tf32<3><<<gemm_grid, 256>>>(pO, Wo, out, MR, DMODEL, DMODEL);
}

// round 4
// speedup vs baseline: 2.9921x; 1.2880x over previous
#include <cuda_runtime.h>
#include <cuda_bf16.h>
#include <math.h>

#define SEQL   2048
#define BATCH  2
#define DMODEL 1024
#define NHEADS 16
#define DHEAD  64
#define MR     (BATCH * SEQL)   // 4096 rows
#define NSEG   16
#define SEGROWS (SEQL / NSEG)   // 128
#define KP     (DMODEL / 2)     // 512 bf16-pair columns

// ---------------- scratch ----------------
__device__ float    g_Q[(size_t)MR * DMODEL];          // f32 (LN'd)
__device__ float    g_K[(size_t)MR * DMODEL];
__device__ float    g_V[(size_t)MR * DMODEL];
__device__ unsigned g_Qt[(size_t)MR * DMODEL];         // tf32 bits
__device__ unsigned g_Kt[(size_t)MR * DMODEL];
__device__ unsigned g_Xh[(size_t)MR * KP];             // bf16 pair splits
__device__ unsigned g_Xl[(size_t)MR * KP];
__device__ unsigned g_Wvh[(size_t)DMODEL * KP];
__device__ unsigned g_Wvl[(size_t)DMODEL * KP];
__device__ unsigned g_Woh[(size_t)DMODEL * KP];
__device__ unsigned g_Wol[(size_t)DMODEL * KP];
__device__ unsigned g_Vth[(size_t)BATCH * NHEADS * DHEAD * (SEQL / 2)];  // [bh][d][n-pairs]
__device__ unsigned g_Vtl[(size_t)BATCH * NHEADS * DHEAD * (SEQL / 2)];
__device__ unsigned g_Oh[(size_t)MR * KP];
__device__ unsigned g_Ol[(size_t)MR * KP];
__device__ float    g_F[(size_t)BATCH * SEQL * SEQL];
__device__ float    g_P[(size_t)BATCH * NSEG * SEQL];

// ---------------- helpers ----------------
__device__ __forceinline__ unsigned f2t(float x) {
    unsigned r;
    asm("cvt.rna.tf32.f32 %0, %1;" : "=r"(r) : "f"(x));
    return r;
}

// split (x0,x1) into bf16x2 hi (packed, x0 low half) and bf16x2 lo (residuals)
__device__ __forceinline__ void bsplit(float x0, float x1, unsigned& h, unsigned& l) {
    asm("cvt.rn.bf16x2.f32 %0, %1, %2;" : "=r"(h) : "f"(x1), "f"(x0));
    __nv_bfloat162 hb = *reinterpret_cast<__nv_bfloat162*>(&h);
    float2 hf = __bfloat1622float2(hb);
    float r0 = x0 - hf.x, r1 = x1 - hf.y;
    asm("cvt.rn.bf16x2.f32 %0, %1, %2;" : "=r"(l) : "f"(r1), "f"(r0));
}

#define MMA(C, A0, A1, A2, A3, B0, B1)                                         \
    asm volatile(                                                              \
        "mma.sync.aligned.m16n8k8.row.col.f32.tf32.tf32.f32 "                  \
        "{%0,%1,%2,%3},{%4,%5,%6,%7},{%8,%9},{%0,%1,%2,%3};"                   \
        : "+f"((C)[0]), "+f"((C)[1]), "+f"((C)[2]), "+f"((C)[3])               \
        : "r"(A0), "r"(A1), "r"(A2), "r"(A3), "r"(B0), "r"(B1))

#define MMAB(C, A0, A1, A2, A3, B0, B1)                                        \
    asm volatile(                                                              \
        "mma.sync.aligned.m16n8k16.row.col.f32.bf16.bf16.f32 "                 \
        "{%0,%1,%2,%3},{%4,%5,%6,%7},{%8,%9},{%0,%1,%2,%3};"                   \
        : "+f"((C)[0]), "+f"((C)[1]), "+f"((C)[2]), "+f"((C)[3])               \
        : "r"(A0), "r"(A1), "r"(A2), "r"(A3), "r"(B0), "r"(B1))

// ---------------- split f32 stream into bf16 hi/lo packed pairs ----------------
__global__ __launch_bounds__(256) void split_pairs(const float* __restrict__ src,
                                                   unsigned* __restrict__ h,
                                                   unsigned* __restrict__ l, int npairs) {
    int i = blockIdx.x * 256 + threadIdx.x;
    if (i < npairs) {
        float2 v = ((const float2*)src)[i];
        unsigned hh, ll;
        bsplit(v.x, v.y, hh, ll);
        h[i] = hh;
        l[i] = ll;
    }
}

// ---------------- GEMM tf32 x3 (Q/K projections; proven path) ----------------
template <int SPLIT>
__global__ __launch_bounds__(256) void gemm_tf32(const float* __restrict__ A,
                                                 const float* __restrict__ B,
                                                 float* __restrict__ Y,
                                                 int M, int N, int K) {
    __shared__ float As[128][36];
    __shared__ float Bs[128][36];
    const int tid = threadIdx.x, lane = tid & 31, warp = tid >> 5;
    const int g = lane >> 2, tg = lane & 3;
    const int wm = warp >> 2, wn = warp & 3;
    const int m0 = blockIdx.y * 128, n0 = blockIdx.x * 128;
    const int lrow = tid >> 3, lcol = (tid & 7) * 4;

    float c[4][4][4] = {};

    for (int k0 = 0; k0 < K; k0 += 32) {
#pragma unroll
        for (int it = 0; it < 4; it++) {
            int r = lrow + it * 32;
            *(float4*)&As[r][lcol] = *(const float4*)&A[(size_t)(m0 + r) * K + k0 + lcol];
            *(float4*)&Bs[r][lcol] = *(const float4*)&B[(size_t)(n0 + r) * K + k0 + lcol];
        }
        __syncthreads();
#pragma unroll
        for (int kc = 0; kc < 4; kc++) {
            unsigned bh[4][2], bl[4][2];
#pragma unroll
            for (int ni = 0; ni < 4; ni++) {
                int nb = wn * 32 + ni * 8;
                float b0 = Bs[nb + g][kc * 8 + tg];
                float b1 = Bs[nb + g][kc * 8 + tg + 4];
                bh[ni][0] = f2t(b0);
                bh[ni][1] = f2t(b1);
                if (SPLIT == 3) {
                    bl[ni][0] = f2t(b0 - __uint_as_float(bh[ni][0]));
                    bl[ni][1] = f2t(b1 - __uint_as_float(bh[ni][1]));
                }
            }
#pragma unroll
            for (int mi = 0; mi < 4; mi++) {
                int rm = wm * 64 + mi * 16;
                float a0 = As[rm + g][kc * 8 + tg];
                float a1 = As[rm + g + 8][kc * 8 + tg];
                float a2 = As[rm + g][kc * 8 + tg + 4];
                float a3 = As[rm + g + 8][kc * 8 + tg + 4];
                unsigned ah0 = f2t(a0), ah1 = f2t(a1), ah2 = f2t(a2), ah3 = f2t(a3);
                unsigned al0 = 0, al1 = 0, al2 = 0, al3 = 0;
                if (SPLIT == 3) {
                    al0 = f2t(a0 - __uint_as_float(ah0));
                    al1 = f2t(a1 - __uint_as_float(ah1));
                    al2 = f2t(a2 - __uint_as_float(ah2));
                    al3 = f2t(a3 - __uint_as_float(ah3));
                }
#pragma unroll
                for (int ni = 0; ni < 4; ni++) {
                    MMA(c[mi][ni], ah0, ah1, ah2, ah3, bh[ni][0], bh[ni][1]);
                    if (SPLIT == 3) {
                        MMA(c[mi][ni], ah0, ah1, ah2, ah3, bl[ni][0], bl[ni][1]);
                        MMA(c[mi][ni], al0, al1, al2, al3, bh[ni][0], bh[ni][1]);
                    }
                }
            }
        }
        __syncthreads();
    }

#pragma unroll
    for (int mi = 0; mi < 4; mi++)
#pragma unroll
        for (int ni = 0; ni < 4; ni++) {
            int r = m0 + wm * 64 + mi * 16 + g;
            int col = n0 + wn * 32 + ni * 8 + 2 * tg;
            *(float2*)&Y[(size_t)r * N + col] = make_float2(c[mi][ni][0], c[mi][ni][1]);
            *(float2*)&Y[(size_t)(r + 8) * N + col] = make_float2(c[mi][ni][2], c[mi][ni][3]);
        }
}

// ---------------- GEMM bf16 x3: Y[M,N] = A·B^T, A/B given as hi/lo packed pairs --------
__global__ __launch_bounds__(256) void gemm_bf3(const unsigned* __restrict__ Ah,
                                                const unsigned* __restrict__ Al,
                                                const unsigned* __restrict__ Bh,
                                                const unsigned* __restrict__ Bl,
                                                float* __restrict__ Y,
                                                int M, int N, int Kp) {
    __shared__ unsigned sAh[128 * 20], sAl[128 * 20];
    __shared__ unsigned sBh[128 * 20], sBl[128 * 20];
    const int tid = threadIdx.x, lane = tid & 31, warp = tid >> 5;
    const int g = lane >> 2, tg = lane & 3;
    const int wm = warp >> 2, wn = warp & 3;
    const int m0 = blockIdx.y * 128, n0 = blockIdx.x * 128;

    float c[4][4][4] = {};

    for (int k0 = 0; k0 < Kp; k0 += 16) {
#pragma unroll
        for (int t = 0; t < 2; t++) {
            int idx = tid + t * 256;          // 0..511 uint4 slots
            int r = idx >> 2, c4 = (idx & 3) * 4;
            *(uint4*)&sAh[r * 20 + c4] = *(const uint4*)&Ah[(size_t)(m0 + r) * Kp + k0 + c4];
            *(uint4*)&sAl[r * 20 + c4] = *(const uint4*)&Al[(size_t)(m0 + r) * Kp + k0 + c4];
            *(uint4*)&sBh[r * 20 + c4] = *(const uint4*)&Bh[(size_t)(n0 + r) * Kp + k0 + c4];
            *(uint4*)&sBl[r * 20 + c4] = *(const uint4*)&Bl[(size_t)(n0 + r) * Kp + k0 + c4];
        }
        __syncthreads();
#pragma unroll
        for (int kc = 0; kc < 2; kc++) {
            unsigned bh[4][2], bl[4][2];
#pragma unroll
            for (int ni = 0; ni < 4; ni++) {
                int nb = (wn * 32 + ni * 8 + g) * 20 + kc * 8 + tg;
                bh[ni][0] = sBh[nb];
                bh[ni][1] = sBh[nb + 4];
                bl[ni][0] = sBl[nb];
                bl[ni][1] = sBl[nb + 4];
            }
#pragma unroll
            for (int mi = 0; mi < 4; mi++) {
                int r1 = (wm * 64 + mi * 16 + g) * 20 + kc * 8 + tg;
                int r2 = r1 + 8 * 20;
                unsigned ah0 = sAh[r1], ah1 = sAh[r2], ah2 = sAh[r1 + 4], ah3 = sAh[r2 + 4];
                unsigned al0 = sAl[r1], al1 = sAl[r2], al2 = sAl[r1 + 4], al3 = sAl[r2 + 4];
#pragma unroll
                for (int ni = 0; ni < 4; ni++) {
                    MMAB(c[mi][ni], ah0, ah1, ah2, ah3, bh[ni][0], bh[ni][1]);
                    MMAB(c[mi][ni], ah0, ah1, ah2, ah3, bl[ni][0], bl[ni][1]);
                    MMAB(c[mi][ni], al0, al1, al2, al3, bh[ni][0], bh[ni][1]);
                }
            }
        }
        __syncthreads();
    }

#pragma unroll
    for (int mi = 0; mi < 4; mi++)
#pragma unroll
        for (int ni = 0; ni < 4; ni++) {
            int r = m0 + wm * 64 + mi * 16 + g;
            int col = n0 + wn * 32 + ni * 8 + 2 * tg;
            *(float2*)&Y[(size_t)r * N + col] = make_float2(c[mi][ni][0], c[mi][ni][1]);
            *(float2*)&Y[(size_t)(r + 8) * N + col] = make_float2(c[mi][ni][2], c[mi][ni][3]);
        }
}

// ---------------- row LayerNorm (in place) + tf32-truncated copy ----------------
__global__ __launch_bounds__(256) void ln_rows_t(float* __restrict__ Y,
                                                 const float* __restrict__ g,
                                                 const float* __restrict__ b,
                                                 unsigned* __restrict__ T) {
    const int row = blockIdx.x;
    float* y = Y + (size_t)row * DMODEL;
    unsigned* t = T + (size_t)row * DMODEL;
    __shared__ float red[256];

    float s = 0.f;
    for (int i = threadIdx.x; i < DMODEL; i += 256) s += y[i];
    red[threadIdx.x] = s;
    __syncthreads();
    for (int o = 128; o > 0; o >>= 1) {
        if (threadIdx.x < o) red[threadIdx.x] += red[threadIdx.x + o];
        __syncthreads();
    }
    const float mu = red[0] * (1.0f / DMODEL);
    __syncthreads();

    float v = 0.f;
    for (int i = threadIdx.x; i < DMODEL; i += 256) {
        float d = y[i] - mu;
        v += d * d;
    }
    red[threadIdx.x] = v;
    __syncthreads();
    for (int o = 128; o > 0; o >>= 1) {
        if (threadIdx.x < o) red[threadIdx.x] += red[threadIdx.x + o];
        __syncthreads();
    }
    const float rstd = rsqrtf(red[0] * (1.0f / DMODEL) + 1e-5f);
    __syncthreads();

    for (int i = threadIdx.x; i < DMODEL; i += 256) {
        float val = (y[i] - mu) * rstd * g[i] + b[i];
        y[i] = val;
        t[i] = f2t(val);
    }
}

// ---------------- V transpose + bf16 split: g_V[b,n,h*64+d] -> Vt[bh][d][n-pair] ----------
__global__ __launch_bounds__(256) void vt_split() {
    __shared__ float tile[64][68];   // stride 68 (mult of 4): float4-safe, 17 float4/row spreads banks
    const int b = blockIdx.z, h = blockIdx.y, n0 = blockIdx.x * 64;
    const int tid = threadIdx.x;
#pragma unroll
    for (int t = 0; t < 4; t++) {
        int idx = tid + t * 256;              // 1024 float4
        int r = idx >> 4, c4 = (idx & 15) * 4;
        *(float4*)&tile[r][c4] =
            *(const float4*)&g_V[(size_t)(b * SEQL + n0 + r) * DMODEL + h * DHEAD + c4];
    }
    __syncthreads();
#pragma unroll
    for (int t = 0; t < 8; t++) {
        int idx = tid + t * 256;              // 2048 u32 outputs
        int d = idx >> 5, j = idx & 31;
        unsigned hh, ll;
        bsplit(tile[2 * j][d], tile[2 * j + 1][d], hh, ll);
        size_t off = ((size_t)((b * NHEADS + h) * DHEAD + d)) * (SEQL / 2) + (n0 >> 1) + j;
        g_Vth[off] = hh;
        g_Vtl[off] = ll;
    }
}

// ---------------- head-0 scores via tf32 x3 (proven path) ----------------
__global__ __launch_bounds__(256) void head0_tc() {
    __shared__ float As[128][36];
    __shared__ float Bs[128][36];
    const int tid = threadIdx.x, lane = tid & 31, warp = tid >> 5;
    const int g = lane >> 2, tg = lane & 3;
    const int wm = warp >> 2, wn = warp & 3;
    const int bb = blockIdx.z;
    const int r0 = blockIdx.y * 128, mm0 = blockIdx.x * 128;
    const float* Aq = g_Q + (size_t)(bb * SEQL + r0) * DMODEL;
    const float* Bk = g_K + (size_t)(bb * SEQL + mm0) * DMODEL;
    const int lrow = tid >> 3, lcol = (tid & 7) * 4;

    float c[4][4][4] = {};

    for (int k0 = 0; k0 < 64; k0 += 32) {
#pragma unroll
        for (int it = 0; it < 4; it++) {
            int r = lrow + it * 32;
            *(float4*)&As[r][lcol] = *(const float4*)&Aq[(size_t)r * DMODEL + k0 + lcol];
            *(float4*)&Bs[r][lcol] = *(const float4*)&Bk[(size_t)r * DMODEL + k0 + lcol];
        }
        __syncthreads();
#pragma unroll
        for (int kc = 0; kc < 4; kc++) {
            unsigned bh[4][2], bl[4][2];
#pragma unroll
            for (int ni = 0; ni < 4; ni++) {
                int nb = wn * 32 + ni * 8;
                float b0 = Bs[nb + g][kc * 8 + tg];
                float b1 = Bs[nb + g][kc * 8 + tg + 4];
                bh[ni][0] = f2t(b0);
                bh[ni][1] = f2t(b1);
                bl[ni][0] = f2t(b0 - __uint_as_float(bh[ni][0]));
                bl[ni][1] = f2t(b1 - __uint_as_float(bh[ni][1]));
            }
#pragma unroll
            for (int mi = 0; mi < 4; mi++) {
                int rm = wm * 64 + mi * 16;
                float a0 = As[rm + g][kc * 8 + tg];
                float a1 = As[rm + g + 8][kc * 8 + tg];
                float a2 = As[rm + g][kc * 8 + tg + 4];
                float a3 = As[rm + g + 8][kc * 8 + tg + 4];
                unsigned ah0 = f2t(a0), ah1 = f2t(a1), ah2 = f2t(a2), ah3 = f2t(a3);
                unsigned al0 = f2t(a0 - __uint_as_float(ah0));
                unsigned al1 = f2t(a1 - __uint_as_float(ah1));
                unsigned al2 = f2t(a2 - __uint_as_float(ah2));
                unsigned al3 = f2t(a3 - __uint_as_float(ah3));
#pragma unroll
                for (int ni = 0; ni < 4; ni++) {
                    MMA(c[mi][ni], ah0, ah1, ah2, ah3, bh[ni][0], bh[ni][1]);
                    MMA(c[mi][ni], ah0, ah1, ah2, ah3, bl[ni][0], bl[ni][1]);
                    MMA(c[mi][ni], al0, al1, al2, al3, bh[ni][0], bh[ni][1]);
                }
            }
        }
        __syncthreads();
    }

#pragma unroll
    for (int mi = 0; mi < 4; mi++)
#pragma unroll
        for (int ni = 0; ni < 4; ni++) {
            int r1 = r0 + wm * 64 + mi * 16 + g;
            int r2 = r1 + 8;
            int m = mm0 + wn * 32 + ni * 8 + 2 * tg;
            float v0 = c[mi][ni][0] * 0.125f;
            float v1 = c[mi][ni][1] * 0.125f;
            float v2 = c[mi][ni][2] * 0.125f;
            float v3 = c[mi][ni][3] * 0.125f;
            v0 = (m >= 1 && m < r1) ? fmaxf(v0, 0.f) : 0.f;
            v1 = (m + 1 < r1) ? fmaxf(v1, 0.f) : 0.f;
            v2 = (m >= 1 && m < r2) ? fmaxf(v2, 0.f) : 0.f;
            v3 = (m + 1 < r2) ? fmaxf(v3, 0.f) : 0.f;
            *(float2*)&g_F[(size_t)(bb * SEQL + r1) * SEQL + m] = make_float2(v0, v1);
            *(float2*)&g_F[(size_t)(bb * SEQL + r2) * SEQL + m] = make_float2(v2, v3);
        }
}

// ---------------- 3-pass exclusive column scan ----------------
__global__ __launch_bounds__(256) void seg_sum() {
    const int m = blockIdx.x * 256 + threadIdx.x;
    const int seg = blockIdx.y, b = blockIdx.z;
    const float* base = g_F + (size_t)(b * SEQL + seg * SEGROWS) * SEQL + m;
    float s = 0.f;
#pragma unroll 4
    for (int r = 0; r < SEGROWS; r++) s += base[(size_t)r * SEQL];
    g_P[(size_t)(b * NSEG + seg) * SEQL + m] = s;
}

__global__ __launch_bounds__(256) void seg_scan() {
    const int m = blockIdx.x * 256 + threadIdx.x;
    const int b = blockIdx.y;
    float acc = 0.f;
#pragma unroll
    for (int s = 0; s < NSEG; s++) {
        size_t idx = (size_t)(b * NSEG + s) * SEQL + m;
        float v = g_P[idx];
        g_P[idx] = acc;
        acc += v;
    }
}

__global__ __launch_bounds__(256) void final_scan() {
    const int m = blockIdx.x * 256 + threadIdx.x;
    const int seg = blockIdx.y, b = blockIdx.z;
    float acc = g_P[(size_t)(b * NSEG + seg) * SEQL + m];
    float* base = g_F + (size_t)(b * SEQL + seg * SEGROWS) * SEQL + m;
#pragma unroll 4
    for (int r = 0; r < SEGROWS; r++) {
        float c = base[(size_t)r * SEQL];
        base[(size_t)r * SEQL] = acc;
        acc += c;
    }
}

// ---------------- flash attention: QK tf32x1 (pre-truncated), PV bf16x3 -------------
__global__ __launch_bounds__(128) void attn_bf() {
    __shared__ unsigned sKt[64 * 68];
    __shared__ unsigned sVh[64 * 36], sVl[64 * 36];
    const int b = blockIdx.z, h = blockIdx.y;
    const int qt = (int)gridDim.x - 1 - (int)blockIdx.x;
    const int q0 = qt * 64;
    const int tid = threadIdx.x, lane = tid & 31, w = tid >> 5;
    const int g = lane >> 2, tg = lane & 3;

    // Q tf32 fragments from global (one-time)
    unsigned qa[8][4];
    const size_t qr1 = (size_t)(b * SEQL + q0 + w * 16 + g) * DMODEL + h * DHEAD;
    const size_t qr2 = qr1 + 8 * DMODEL;
#pragma unroll
    for (int kc = 0; kc < 8; kc++) {
        qa[kc][0] = g_Qt[qr1 + kc * 8 + tg];
        qa[kc][1] = g_Qt[qr2 + kc * 8 + tg];
        qa[kc][2] = g_Qt[qr1 + kc * 8 + tg + 4];
        qa[kc][3] = g_Qt[qr2 + kc * 8 + tg + 4];
    }

    float o[8][4] = {};
    float qm0 = -1e30f, qm1 = -1e30f, lsum0 = 0.f, lsum1 = 0.f;

    for (int kt = 0; kt <= qt; kt++) {
        const int m0 = kt * 64;
        // stage K (tf32 u32) + V (bf16 hi/lo pairs, d-major)
#pragma unroll
        for (int t = 0; t < 8; t++) {
            int idx = tid + t * 128;          // 1024 uint4
            int r = idx >> 4, c4 = (idx & 15) * 4;
            *(uint4*)&sKt[r * 68 + c4] =
                *(const uint4*)&g_Kt[(size_t)(b * SEQL + m0 + r) * DMODEL + h * DHEAD + c4];
        }
        const size_t vbase = (size_t)((b * NHEADS + h) * DHEAD) * (SEQL / 2) + (m0 >> 1);
#pragma unroll
        for (int t = 0; t < 4; t++) {
            int idx = tid + t * 128;          // 512 uint4 per buffer
            int r = idx >> 3, c4 = (idx & 7) * 4;
            *(uint4*)&sVh[r * 36 + c4] = *(const uint4*)&g_Vth[vbase + (size_t)r * (SEQL / 2) + c4];
            *(uint4*)&sVl[r * 36 + c4] = *(const uint4*)&g_Vtl[vbase + (size_t)r * (SEQL / 2) + c4];
        }
        __syncthreads();

        // S = Q·K^T (tf32 x1)
        float sc[8][4] = {};
#pragma unroll
        for (int kc = 0; kc < 8; kc++) {
#pragma unroll
            for (int ni = 0; ni < 8; ni++) {
                unsigned b0 = sKt[(ni * 8 + g) * 68 + kc * 8 + tg];
                unsigned b1 = sKt[(ni * 8 + g) * 68 + kc * 8 + tg + 4];
                MMA(sc[ni], qa[kc][0], qa[kc][1], qa[kc][2], qa[kc][3], b0, b1);
            }
        }

        // online softmax
        const bool diag = (kt == qt);
        const int lr1 = w * 16 + g, lr2 = lr1 + 8;
        const size_t frow1 = (size_t)(b * SEQL + q0 + lr1) * SEQL + m0;
        const size_t frow2 = (size_t)(b * SEQL + q0 + lr2) * SEQL + m0;
        float mx0 = -1e30f, mx1 = -1e30f;
#pragma unroll
        for (int ni = 0; ni < 8; ni++) {
            int cl = ni * 8 + 2 * tg;
            float2 f1 = *(const float2*)&g_F[frow1 + cl];
            float2 f2 = *(const float2*)&g_F[frow2 + cl];
            float v0 = sc[ni][0] * 0.125f - f1.x;
            float v1 = sc[ni][1] * 0.125f - f1.y;
            float v2 = sc[ni][2] * 0.125f - f2.x;
            float v3 = sc[ni][3] * 0.125f - f2.y;
            if (diag) {
                if (cl > lr1) v0 = -1e30f;
                if (cl + 1 > lr1) v1 = -1e30f;
                if (cl > lr2) v2 = -1e30f;
                if (cl + 1 > lr2) v3 = -1e30f;
            }
            sc[ni][0] = v0; sc[ni][1] = v1; sc[ni][2] = v2; sc[ni][3] = v3;
            mx0 = fmaxf(mx0, fmaxf(v0, v1));
            mx1 = fmaxf(mx1, fmaxf(v2, v3));
        }
        mx0 = fmaxf(mx0, __shfl_xor_sync(0xffffffffu, mx0, 1));
        mx0 = fmaxf(mx0, __shfl_xor_sync(0xffffffffu, mx0, 2));
        mx1 = fmaxf(mx1, __shfl_xor_sync(0xffffffffu, mx1, 1));
        mx1 = fmaxf(mx1, __shfl_xor_sync(0xffffffffu, mx1, 2));
        const float nm0 = fmaxf(qm0, mx0), nm1 = fmaxf(qm1, mx1);
        const float s0 = __expf(qm0 - nm0), s1 = __expf(qm1 - nm1);
        float ps0 = 0.f, ps1 = 0.f;
#pragma unroll
        for (int ni = 0; ni < 8; ni++) {
            float e0 = __expf(sc[ni][0] - nm0);
            float e1 = __expf(sc[ni][1] - nm0);
            float e2 = __expf(sc[ni][2] - nm1);
            float e3 = __expf(sc[ni][3] - nm1);
            sc[ni][0] = e0; sc[ni][1] = e1; sc[ni][2] = e2; sc[ni][3] = e3;
            ps0 += e0 + e1;
            ps1 += e2 + e3;
            o[ni][0] *= s0; o[ni][1] *= s0; o[ni][2] *= s1; o[ni][3] *= s1;
        }
        ps0 += __shfl_xor_sync(0xffffffffu, ps0, 1);
        ps0 += __shfl_xor_sync(0xffffffffu, ps0, 2);
        ps1 += __shfl_xor_sync(0xffffffffu, ps1, 1);
        ps1 += __shfl_xor_sync(0xffffffffu, ps1, 2);
        lsum0 = lsum0 * s0 + ps0;
        lsum1 = lsum1 * s1 + ps1;
        qm0 = nm0; qm1 = nm1;

        // O += P·V  (bf16 x3; P split in-register, no smem round-trip)
#pragma unroll
        for (int kc2 = 0; kc2 < 4; kc2++) {
            unsigned ph0, pl0, ph1, pl1, ph2, pl2, ph3, pl3;
            bsplit(sc[kc2 * 2][0], sc[kc2 * 2][1], ph0, pl0);
            bsplit(sc[kc2 * 2][2], sc[kc2 * 2][3], ph1, pl1);
            bsplit(sc[kc2 * 2 + 1][0], sc[kc2 * 2 + 1][1], ph2, pl2);
            bsplit(sc[kc2 * 2 + 1][2], sc[kc2 * 2 + 1][3], ph3, pl3);
#pragma unroll
            for (int ni = 0; ni < 8; ni++) {
                int vb = (ni * 8 + g) * 36 + kc2 * 8 + tg;
                unsigned vh0 = sVh[vb], vh1 = sVh[vb + 4];
                unsigned vl0 = sVl[vb], vl1 = sVl[vb + 4];
                MMAB(o[ni], ph0, ph1, ph2, ph3, vh0, vh1);
                MMAB(o[ni], ph0, ph1, ph2, ph3, vl0, vl1);
                MMAB(o[ni], pl0, pl1, pl2, pl3, vh0, vh1);
            }
        }
        __syncthreads();
    }

    // epilogue: normalize and store bf16 hi/lo pairs directly
    const float i0 = 1.0f / lsum0, i1 = 1.0f / lsum1;
    const size_t or1 = (size_t)(b * SEQL + q0 + w * 16 + g) * KP + h * 32;
    const size_t or2 = or1 + 8 * KP;
#pragma unroll
    for (int ni = 0; ni < 8; ni++) {
        unsigned hh, ll;
        bsplit(o[ni][0] * i0, o[ni][1] * i0, hh, ll);
        g_Oh[or1 + ni * 4 + tg] = hh;
        g_Ol[or1 + ni * 4 + tg] = ll;
        bsplit(o[ni][2] * i1, o[ni][3] * i1, hh, ll);
        g_Oh[or2 + ni * 4 + tg] = hh;
        g_Ol[or2 + ni * 4 + tg] = ll;
    }
}

// ---------------- launch ----------------
extern "C" void kernel_launch(void* const* d_in, const int* in_sizes, int n_in,
                              void* d_out, int out_size) {
    const float* X  = (const float*)d_in[0];
    const float* Wq = (const float*)d_in[1];
    const float* Wk = (const float*)d_in[2];
    const float* Wv = (const float*)d_in[3];
    const float* Wo = (const float*)d_in[4];
    const float* gq = (const float*)d_in[5];
    const float* bq = (const float*)d_in[6];
    const float* gk = (const float*)d_in[7];
    const float* bk = (const float*)d_in[8];
    float* out = (float*)d_out;

    float *pQ, *pK, *pV;
    unsigned *pQt, *pKt, *pXh, *pXl, *pWvh, *pWvl, *pWoh, *pWol, *pOh, *pOl;
    cudaGetSymbolAddress((void**)&pQ, g_Q);
    cudaGetSymbolAddress((void**)&pK, g_K);
    cudaGetSymbolAddress((void**)&pV, g_V);
    cudaGetSymbolAddress((void**)&pQt, g_Qt);
    cudaGetSymbolAddress((void**)&pKt, g_Kt);
    cudaGetSymbolAddress((void**)&pXh, g_Xh);
    cudaGetSymbolAddress((void**)&pXl, g_Xl);
    cudaGetSymbolAddress((void**)&pWvh, g_Wvh);
    cudaGetSymbolAddress((void**)&pWvl, g_Wvl);
    cudaGetSymbolAddress((void**)&pWoh, g_Woh);
    cudaGetSymbolAddress((void**)&pWol, g_Wol);
    cudaGetSymbolAddress((void**)&pOh, g_Oh);
    cudaGetSymbolAddress((void**)&pOl, g_Ol);

    const dim3 gemm_grid(DMODEL / 128, MR / 128);   // (8, 32)

    split_pairs<<<(MR * KP + 255) / 256, 256>>>(X, pXh, pXl, MR * KP);
    split_pairs<<<(DMODEL * KP + 255) / 256, 256>>>(Wv, pWvh, pWvl, DMODEL * KP);
    split_pairs<<<(DMODEL * KP + 255) / 256, 256>>>(Wo, pWoh, pWol, DMODEL * KP);

    gemm_tf32<3><<<gemm_grid, 256>>>(X, Wq, pQ, MR, DMODEL, DMODEL);
    gemm_tf32<3><<<gemm_grid, 256>>>(X, Wk, pK, MR, DMODEL, DMODEL);
    gemm_bf3<<<gemm_grid, 256>>>(pXh, pXl, pWvh, pWvl, pV, MR, DMODEL, KP);

    ln_rows_t<<<MR, 256>>>(pQ, gq, bq, pQt);
    ln_rows_t<<<MR, 256>>>(pK, gk, bk, pKt);
    vt_split<<<dim3(SEQL / 64, NHEADS, BATCH), 256>>>();

    head0_tc<<<dim3(SEQL / 128, SEQL / 128, BATCH), 256>>>();
    seg_sum<<<dim3(SEQL / 256, NSEG, BATCH), 256>>>();
    seg_scan<<<dim3(SEQL / 256, BATCH), 256>>>();
    final_scan<<<dim3(SEQL / 256, NSEG, BATCH), 256>>>();

    attn_bf<<<dim3(SEQL / 64, NHEADS, BATCH), 128>>>();

    gemm_bf3<<<gemm_grid, 256>>>(pOh, pOl, pWoh, pWol, out, MR, DMODEL, KP);
}